// round 1
// baseline (speedup 1.0000x reference)
#include <cuda_runtime.h>
#include <math.h>

// ---------------------------------------------------------------------------
// MPPI: N=16384 rollouts, H=64 steps, S=128 state, C=32 controls.
//   x_{t+1} = x_t + DT*tanh(x_t A^T + u_t B^T)
//   cost_n  = sum_{t=0..H} ||x_t||^2 + 0.1 * sum u^2   (Q=1, R=0.1)
//   w = softmax(-cost); out = [ sum_n w_n a_n  (H,C) ;  opt rollout (H+1,S) ]
// ---------------------------------------------------------------------------

#define S_DIM 128
#define C_DIM 32
#define H_DIM 64
#define KD    160        // S + C fused inner dimension
#define WPAD  132        // padded row length of W in smem (bank stagger)
#define MB    64         // samples per block
#define DT_F  0.05f
#define NMAX  16384
#define NCHUNK 32

__device__ double g_costs[NMAX];
__device__ double g_wtmp[NMAX];
__device__ float  g_weights[NMAX];
__device__ double g_part[NCHUNK * H_DIM * C_DIM];

// ---------------- packed fp32x2 helpers (Blackwell dual-rate FFMA) ----------
__device__ __forceinline__ unsigned long long pack2(float lo, float hi) {
    unsigned long long r;
    asm("mov.b64 %0, {%1, %2};" : "=l"(r) : "f"(lo), "f"(hi));
    return r;
}
__device__ __forceinline__ void unpack2(unsigned long long v, float &lo, float &hi) {
    asm("mov.b64 {%0, %1}, %2;" : "=f"(lo), "=f"(hi) : "l"(v));
}
__device__ __forceinline__ void fma2(unsigned long long &d,
                                     unsigned long long a, unsigned long long b) {
    asm("fma.rn.f32x2 %0, %1, %2, %3;" : "=l"(d) : "l"(a), "l"(b), "l"(d));
}

// tanh via 2 MUFU ops: tanh(x) = 1 - 2/(exp(2x)+1).  Abs error ~1e-7.
__device__ __forceinline__ float tanh_fast(float x) {
    float xc = fminf(fmaxf(x, -15.f), 15.f);
    float e, r;
    asm("ex2.approx.f32 %0, %1;" : "=f"(e) : "f"(xc * 2.885390081777927f)); // 2/ln2
    asm("rcp.approx.f32 %0, %1;" : "=f"(r) : "f"(e + 1.0f));
    return fmaf(-2.0f, r, 1.0f);
}

// ---------------------------------------------------------------------------
// K1: rollout + per-sample cost.  One CTA = 64 samples, 256 threads (16x16),
// thread tile 4 (samples) x 8 (states).  Z[k][m] and W[k][s] stay in SMEM for
// all 64 steps; only the per-step controls stream in from HBM.
// ---------------------------------------------------------------------------
__global__ __launch_bounds__(256, 1)
void k_rollout(const float* __restrict__ state, const float* __restrict__ A,
               const float* __restrict__ Bm, const float* __restrict__ noises,
               const float* __restrict__ prev, int thr)
{
    extern __shared__ float smem[];
    float* Ws = smem;                 // [KD][WPAD]  (W[k][s] = A[s][k] / B[s][c])
    float* Zs = smem + KD * WPAD;     // [KD][MB]    (x rows 0..127, u rows 128..159)
    __shared__ double redC[MB][16];
    __shared__ double redR[MB][4];

    const int tid = threadIdx.x;
    const int tx  = tid & 15, ty = tid >> 4;
    const int tx4 = tx * 4,   ty8 = ty * 8;
    const int n0  = blockIdx.x * MB;

    // Load W = [A^T ; B^T] transposed into [k][s] layout (coalesced A reads).
    for (int idx = tid; idx < KD * S_DIM; idx += 256) {
        int s = idx / KD, k = idx - s * KD;
        float v = (k < S_DIM) ? A[s * S_DIM + k] : Bm[s * C_DIM + (k - S_DIM)];
        Ws[k * WPAD + s] = v;
    }
    // x_0 broadcast
    for (int idx = tid; idx < S_DIM * MB; idx += 256)
        Zs[idx] = state[idx >> 6];

    // control-loader role: thread handles sample um, quarter uq (8 channels)
    const int um = tid >> 2, uq = tid & 3;
    const int un = n0 + um;
    const float* nsrc = noises + (size_t)un * H_DIM * C_DIM + uq * 8;
    const bool inh = (un < thr);
    double rAcc = 0.0;

    { // u for step 0
        float4 a = *(const float4*)(nsrc);
        float4 b = *(const float4*)(nsrc + 4);
        float v[8] = {a.x,a.y,a.z,a.w,b.x,b.y,b.z,b.w};
        const float* pv = prev + uq * 8;
        float rs = 0.f;
        #pragma unroll
        for (int e = 0; e < 8; e++) {
            float u = v[e] + (inh ? pv[e] : 0.f);
            u = fminf(fmaxf(u, -2.f), 2.f);
            rs += u * u;
            Zs[(S_DIM + uq * 8 + e) * MB + um] = u;
        }
        rAcc += rs;
    }

    double cAcc[4] = {0, 0, 0, 0};

    for (int t = 0; t < H_DIM; t++) {
        __syncthreads();   // x-updates + u-fill from previous step visible

        unsigned long long acc01[8], acc23[8];
        #pragma unroll
        for (int j = 0; j < 8; j++) { acc01[j] = 0ull; acc23[j] = 0ull; }

        const float* zp = Zs + tx4;
        const float* wp = Ws + ty8;
        #pragma unroll 8
        for (int k = 0; k < KD; k++) {
            float4 z  = *(const float4*)(zp + k * MB);
            float4 w0 = *(const float4*)(wp + k * WPAD);
            float4 w1 = *(const float4*)(wp + k * WPAD + 4);
            unsigned long long z01 = pack2(z.x, z.y);
            unsigned long long z23 = pack2(z.z, z.w);
            float wv[8] = {w0.x,w0.y,w0.z,w0.w,w1.x,w1.y,w1.z,w1.w};
            #pragma unroll
            for (int j = 0; j < 8; j++) {
                unsigned long long wd = pack2(wv[j], wv[j]);
                fma2(acc01[j], z01, wd);
                fma2(acc23[j], z23, wd);
            }
        }
        __syncthreads();   // all GEMM reads of Zs done before overwriting

        // x_{t+1} = x_t + DT*tanh(y); accumulate stage cost ||x_t||^2
        float st[4] = {0, 0, 0, 0};
        #pragma unroll
        for (int j = 0; j < 8; j++) {
            float y0, y1, y2, y3;
            unpack2(acc01[j], y0, y1);
            unpack2(acc23[j], y2, y3);
            float* xp = Zs + (ty8 + j) * MB + tx4;
            float4 xo = *(float4*)xp;
            st[0] += xo.x * xo.x; st[1] += xo.y * xo.y;
            st[2] += xo.z * xo.z; st[3] += xo.w * xo.w;
            float4 xn;
            xn.x = xo.x + DT_F * tanh_fast(y0);
            xn.y = xo.y + DT_F * tanh_fast(y1);
            xn.z = xo.z + DT_F * tanh_fast(y2);
            xn.w = xo.w + DT_F * tanh_fast(y3);
            *(float4*)xp = xn;
        }
        cAcc[0] += st[0]; cAcc[1] += st[1]; cAcc[2] += st[2]; cAcc[3] += st[3];

        if (t < H_DIM - 1) {  // u for step t+1 (disjoint smem rows, no extra sync)
            const float* src = nsrc + (size_t)(t + 1) * C_DIM;
            float4 a = *(const float4*)(src);
            float4 b = *(const float4*)(src + 4);
            float v[8] = {a.x,a.y,a.z,a.w,b.x,b.y,b.z,b.w};
            const float* pv = prev + (t + 1) * C_DIM + uq * 8;
            float rs = 0.f;
            #pragma unroll
            for (int e = 0; e < 8; e++) {
                float u = v[e] + (inh ? pv[e] : 0.f);
                u = fminf(fmaxf(u, -2.f), 2.f);
                rs += u * u;
                Zs[(S_DIM + uq * 8 + e) * MB + um] = u;
            }
            rAcc += rs;
        }
    }

    // terminal ||x_H||^2 — each thread reads only its own cells, no sync needed
    {
        float tt[4] = {0, 0, 0, 0};
        #pragma unroll
        for (int j = 0; j < 8; j++) {
            float4 xv = *(const float4*)(Zs + (ty8 + j) * MB + tx4);
            tt[0] += xv.x * xv.x; tt[1] += xv.y * xv.y;
            tt[2] += xv.z * xv.z; tt[3] += xv.w * xv.w;
        }
        cAcc[0] += tt[0]; cAcc[1] += tt[1]; cAcc[2] += tt[2]; cAcc[3] += tt[3];
    }

    #pragma unroll
    for (int i = 0; i < 4; i++) redC[tx4 + i][ty] = cAcc[i];
    redR[um][uq] = rAcc;
    __syncthreads();
    if (tid < MB) {
        double c = 0.0;
        #pragma unroll
        for (int j = 0; j < 16; j++) c += redC[tid][j];
        double ru = redR[tid][0] + redR[tid][1] + redR[tid][2] + redR[tid][3];
        g_costs[n0 + tid] = c + 0.1 * ru;
    }
}

// ---------------------------------------------------------------------------
// K2: softmax over -costs (single block, fp64).
// ---------------------------------------------------------------------------
__global__ void k_softmax(int N)
{
    __shared__ double sm[1024];
    const int tid = threadIdx.x;
    double lmin = 1e300;
    for (int n = tid; n < N; n += 1024) lmin = fmin(lmin, g_costs[n]);
    sm[tid] = lmin; __syncthreads();
    for (int s = 512; s > 0; s >>= 1) {
        if (tid < s) sm[tid] = fmin(sm[tid], sm[tid + s]);
        __syncthreads();
    }
    double cmin = sm[0];
    __syncthreads();
    double ls = 0.0;
    for (int n = tid; n < N; n += 1024) {
        double w = exp(cmin - g_costs[n]);
        g_wtmp[n] = w; ls += w;
    }
    sm[tid] = ls; __syncthreads();
    for (int s = 512; s > 0; s >>= 1) {
        if (tid < s) sm[tid] += sm[tid + s];
        __syncthreads();
    }
    double inv = 1.0 / sm[0];
    for (int n = tid; n < N; n += 1024)
        g_weights[n] = (float)(g_wtmp[n] * inv);
}

// ---------------------------------------------------------------------------
// K3: partial weighted action sum.  grid (NCHUNK, H); block 256 = 8 n-rows x 32 c.
// Softmax is extremely peaked -> warp-uniform skip of negligible weights.
// ---------------------------------------------------------------------------
__global__ void k_wsum(const float* __restrict__ noises,
                       const float* __restrict__ prev, int thr, int N)
{
    const int ch = blockIdx.x, h = blockIdx.y;
    const int c = threadIdx.x & 31, r = threadIdx.x >> 5;
    const int cnt = N / NCHUNK;
    const int n0 = ch * cnt;
    const float pv = prev[h * C_DIM + c];
    double acc = 0.0;
    for (int nn = n0 + r; nn < n0 + cnt; nn += 8) {
        float w = g_weights[nn];
        if (w > 1e-12f) {   // skipped mass <= N*1e-12 -> abs err < 1e-7, safe
            float v = noises[((size_t)nn * H_DIM + h) * C_DIM + c];
            if (nn < thr) v += pv;
            v = fminf(fmaxf(v, -2.f), 2.f);
            acc += (double)w * (double)v;
        }
    }
    __shared__ double s[8][33];
    s[r][c] = acc; __syncthreads();
    if (r == 0) {
        double t = 0.0;
        #pragma unroll
        for (int i = 0; i < 8; i++) t += s[i][c];
        g_part[(ch * H_DIM + h) * C_DIM + c] = t;
    }
}

// K4: reduce partials into optimal_action_seq (deterministic fixed order).
__global__ void k_afinal(float* __restrict__ outA)
{
    int idx = blockIdx.x * 1024 + threadIdx.x;
    if (idx >= H_DIM * C_DIM) return;
    double t = 0.0;
    #pragma unroll
    for (int ch = 0; ch < NCHUNK; ch++) t += g_part[ch * H_DIM * C_DIM + idx];
    outA[idx] = (float)t;
}

// ---------------------------------------------------------------------------
// K5: rollout of the optimal action sequence (single block, 2-way k-split).
// ---------------------------------------------------------------------------
__global__ __launch_bounds__(256, 1)
void k_opt(const float* __restrict__ state, const float* __restrict__ A,
           const float* __restrict__ Bm, const float* __restrict__ outA,
           float* __restrict__ outS)
{
    extern __shared__ float Ws[];     // [KD][WPAD]
    __shared__ float xu[KD];
    __shared__ float part[S_DIM];
    const int tid = threadIdx.x;
    const int s = tid & 127, half = tid >> 7;

    for (int idx = tid; idx < KD * S_DIM; idx += 256) {
        int ss = idx / KD, k = idx - ss * KD;
        Ws[k * WPAD + ss] = (k < S_DIM) ? A[ss * S_DIM + k]
                                        : Bm[ss * C_DIM + (k - S_DIM)];
    }
    if (tid < S_DIM) {
        float x0 = state[tid];
        xu[tid] = x0;
        outS[tid] = x0;               // row 0 of optimal_state_seq
    }
    for (int t = 0; t < H_DIM; t++) {
        if (tid < C_DIM) xu[S_DIM + tid] = outA[t * C_DIM + tid];
        __syncthreads();
        float acc = 0.f;
        const int k0 = half * 80;
        #pragma unroll 8
        for (int k = k0; k < k0 + 80; k++)
            acc = fmaf(xu[k], Ws[k * WPAD + s], acc);
        if (half) part[s] = acc;
        __syncthreads();
        if (!half) {
            float y = acc + part[s];
            float xn = xu[s] + DT_F * tanh_fast(y);
            xu[s] = xn;
            outS[(t + 1) * S_DIM + s] = xn;
        }
        __syncthreads();              // protect xu reads before next overwrite
    }
}

// ---------------------------------------------------------------------------
extern "C" void kernel_launch(void* const* d_in, const int* in_sizes, int n_in,
                              void* d_out, int out_size)
{
    const float* state  = (const float*)d_in[0];
    const float* A      = (const float*)d_in[1];
    const float* Bm     = (const float*)d_in[2];
    const float* noises = (const float*)d_in[3];
    const float* prev   = (const float*)d_in[4];

    int N = in_sizes[3] / (H_DIM * C_DIM);
    if (N > NMAX) N = NMAX;
    int thr = (int)((double)N * (1.0 - 0.2));   // matches python int(N*0.8)

    float* outA = (float*)d_out;
    float* outS = outA + H_DIM * C_DIM;

    const int smem1 = (KD * WPAD + KD * MB) * (int)sizeof(float);   // 125440
    const int smem5 = KD * WPAD * (int)sizeof(float);               // 84480
    cudaFuncSetAttribute(k_rollout, cudaFuncAttributeMaxDynamicSharedMemorySize, smem1);
    cudaFuncSetAttribute(k_opt,     cudaFuncAttributeMaxDynamicSharedMemorySize, smem5);

    k_rollout<<<N / MB, 256, smem1>>>(state, A, Bm, noises, prev, thr);
    k_softmax<<<1, 1024>>>(N);
    dim3 g3(NCHUNK, H_DIM);
    k_wsum<<<g3, 256>>>(noises, prev, thr, N);
    k_afinal<<<2, 1024>>>(outA);
    k_opt<<<1, 256, smem5>>>(state, A, Bm, outA, outS);
}

// round 5
// speedup vs baseline: 1.9956x; 1.9956x over previous
#include <cuda_runtime.h>
#include <cuda_bf16.h>
#include <math.h>
#include <stdint.h>

// ---------------------------------------------------------------------------
// MPPI, N=16384 H=64 S=128 C=32, via incremental split-bf16 mma.sync rollouts.
// y (=x@A^T+u@B^T) lives in fp32 mma accumulators across steps; each step adds
// dY = Dx@A^T + Du@B^T with Dx,Du in bf16 hi+lo (3 cross terms, lo*lo dropped).
// ---------------------------------------------------------------------------

#define S_DIM 128
#define C_DIM 32
#define H_DIM 64
#define DT_F  0.05f
#define NMAX  16384
#define NCHUNK 32
#define MB    128
#define LDW   328        // bf16 elements per Z/W SMEM row (320 used + 8 pad)
#define LDWW  164        // 32-bit words per row
#define WPAD  132

__device__ double g_costs[NMAX];
__device__ double g_wtmp[NMAX];
__device__ float  g_weights[NMAX];
__device__ double g_part[NCHUNK * H_DIM * C_DIM];

// ---------------------------- helpers --------------------------------------
__device__ __forceinline__ uint32_t smem_u32(const void* p) {
    uint32_t a;
    asm("{ .reg .u64 t; cvta.to.shared.u64 t, %1; cvt.u32.u64 %0, t; }"
        : "=r"(a) : "l"(p));
    return a;
}
__device__ __forceinline__ void ldm_x4(uint32_t* r, uint32_t addr) {
    asm volatile("ldmatrix.sync.aligned.m8n8.x4.shared.b16 {%0,%1,%2,%3}, [%4];"
                 : "=r"(r[0]), "=r"(r[1]), "=r"(r[2]), "=r"(r[3]) : "r"(addr));
}
__device__ __forceinline__ void mma16816(float* c, const uint32_t* a, const uint32_t* b) {
    asm volatile(
        "mma.sync.aligned.m16n8k16.row.col.f32.bf16.bf16.f32 "
        "{%0,%1,%2,%3}, {%4,%5,%6,%7}, {%8,%9}, {%0,%1,%2,%3};"
        : "+f"(c[0]), "+f"(c[1]), "+f"(c[2]), "+f"(c[3])
        : "r"(a[0]), "r"(a[1]), "r"(a[2]), "r"(a[3]), "r"(b[0]), "r"(b[1]));
}
// pack 2 floats -> bf16x2: hi = truncated upper halves
__device__ __forceinline__ uint32_t hi2(float a, float b) {
    uint32_t r;
    asm("prmt.b32 %0, %1, %2, 0x7632;"
        : "=r"(r) : "r"(__float_as_uint(a)), "r"(__float_as_uint(b)));
    return r;
}
__device__ __forceinline__ float trunc16(float v) {
    return __uint_as_float(__float_as_uint(v) & 0xFFFF0000u);
}
__device__ __forceinline__ uint32_t lo2(float a, float b) {
    float la = a - trunc16(a), lb = b - trunc16(b);
    uint32_t r;
    asm("cvt.rn.bf16x2.f32 %0, %1, %2;" : "=r"(r) : "f"(lb), "f"(la));
    return r;
}
__device__ __forceinline__ float tanh_fast(float x) {
    float xc = fminf(fmaxf(x, -15.f), 15.f);
    float e, r;
    asm("ex2.approx.f32 %0, %1;" : "=f"(e) : "f"(xc * 2.885390081777927f));
    asm("rcp.approx.f32 %0, %1;" : "=f"(r) : "f"(e + 1.0f));
    return fmaf(-2.0f, r, 1.0f);
}
__device__ __forceinline__ unsigned short hi1(float v) {
    return (unsigned short)(__float_as_uint(v) >> 16);
}
__device__ __forceinline__ unsigned short lo1(float v) {
    __nv_bfloat16 b = __float2bfloat16(v - trunc16(v));
    return *(unsigned short*)&b;
}

// ---------------------------------------------------------------------------
// K1: rollout.  512 threads = 16 warps (4 m-groups x 4 n-groups of 32x32),
// 128 samples per CTA, grid = 128.
// K layout of Z rows / W rows: [Dxh 0..127 | Dxl 128..255 | Duh 256..287 | Dul 288..319]
// ---------------------------------------------------------------------------
__global__ __launch_bounds__(512, 1)
void k_roll(const float* __restrict__ state, const float* __restrict__ A,
            const float* __restrict__ Bm, const float* __restrict__ noises,
            const float* __restrict__ prev, int thr)
{
    extern __shared__ char dynsm[];
    char* zc = (char*)(((uintptr_t)dynsm + 1023) & ~(uintptr_t)1023);
    char* wc = zc + MB * LDW * 2;
    unsigned short* Zh16 = (unsigned short*)zc;
    unsigned short* Wh16 = (unsigned short*)wc;
    uint32_t* Zw = (uint32_t*)zc;
    const uint32_t zb = smem_u32(zc), wb = smem_u32(wc);

    __shared__ double s_cd[512][4];
    __shared__ float  s_uc[4][128];

    const int tid  = threadIdx.x;
    const int wid  = tid >> 5, lane = tid & 31;
    const int m0   = (wid >> 2) * 32, n0 = (wid & 3) * 32;
    const int n0g  = blockIdx.x * MB;

    // ldmatrix lane base addresses (A: rows m, B: rows n), byte units
    const uint32_t aA0 = zb + (uint32_t)(m0 + (lane & 15)) * (LDW * 2) + (lane >> 4) * 16;
    const uint32_t aA1 = aA0 + 16 * LDW * 2;
    const uint32_t aB0 = wb + (uint32_t)(n0 + (lane & 7) + ((lane >> 4) & 1) * 8) * (LDW * 2)
                            + ((lane >> 3) & 1) * 16;
    const uint32_t aB1 = aB0 + 16 * LDW * 2;

    // ---- preamble ----
    #pragma unroll
    for (int i = 0; i < 4; i++) s_cd[tid][i] = 0.0;

    for (int idx = tid; idx < S_DIM * S_DIM; idx += 512) {   // W <- A
        int n = idx >> 7, k = idx & 127;
        float v = A[idx];
        Wh16[n * LDW + k]       = hi1(v);
        Wh16[n * LDW + 128 + k] = lo1(v);
    }
    for (int idx = tid; idx < S_DIM * C_DIM; idx += 512) {   // W <- B
        int n = idx >> 5, cch = idx & 31;
        float v = Bm[idx];
        Wh16[n * LDW + 256 + cch] = hi1(v);
        Wh16[n * LDW + 288 + cch] = lo1(v);
    }
    for (int idx = tid; idx < MB * S_DIM; idx += 512) {      // Z <- x0 (Dx at t=0)
        int mm = idx >> 7, k = idx & 127;
        float v = state[k];
        Zh16[mm * LDW + k]       = hi1(v);
        Zh16[mm * LDW + 128 + k] = lo1(v);
    }

    // u role: sample us, channels uq*8..uq*8+7
    const int us = tid >> 2, uq = tid & 3;
    const bool inh = (n0g + us) < thr;
    const float* up = noises + (size_t)(n0g + us) * (H_DIM * C_DIM) + uq * 8;
    float uold[8];
    float ucost = 0.f;
    {
        float4 f0 = *(const float4*)(up);
        float4 f1 = *(const float4*)(up + 4);
        float uv[8] = {f0.x, f0.y, f0.z, f0.w, f1.x, f1.y, f1.z, f1.w};
        const float* pp = prev + uq * 8;
        #pragma unroll
        for (int e = 0; e < 8; e++) {
            float u = uv[e] + (inh ? pp[e] : 0.f);
            u = fminf(fmaxf(u, -2.f), 2.f);
            ucost += u * u;
            uold[e] = u;
        }
        int bh_ = us * LDWW + 128 + uq * 4;
        #pragma unroll
        for (int e = 0; e < 8; e += 2) {
            Zw[bh_ + (e >> 1)]      = hi2(uold[e], uold[e + 1]);   // Duh
            Zw[bh_ + 16 + (e >> 1)] = lo2(uold[e], uold[e + 1]);   // Dul
        }
    }

    // x registers aligned with C-fragment cells: idx (ms*4+nt)*4 + j
    float c[32], xr[32];
    #pragma unroll
    for (int ms = 0; ms < 2; ms++)
        #pragma unroll
        for (int nt = 0; nt < 4; nt++)
            #pragma unroll
            for (int j = 0; j < 4; j++) {
                int col = n0 + nt * 8 + (lane & 3) * 2 + (j & 1);
                xr[(ms * 4 + nt) * 4 + j] = state[col];
                c[(ms * 4 + nt) * 4 + j] = 0.f;
            }

    float win[4] = {0.f, 0.f, 0.f, 0.f};
    __syncthreads();

    // ---- main loop ----
    #pragma unroll 1
    for (int t = 0; t < H_DIM; t++) {
        // mma phase: C += Dx@A^T + Du@B^T  (3 split terms)
        #pragma unroll
        for (int ch = 0; ch < 10; ch++) {
            const int kh = (ch < 8) ? ch * 16 : (256 + (ch - 8) * 16);
            const int kl = kh + ((ch < 8) ? 128 : 32);
            uint32_t ah[8], al[8], bh[8], bl[8];
            ldm_x4(ah,     aA0 + kh * 2);
            ldm_x4(ah + 4, aA1 + kh * 2);
            ldm_x4(bh,     aB0 + kh * 2);
            ldm_x4(bh + 4, aB1 + kh * 2);
            ldm_x4(bl,     aB0 + kl * 2);
            ldm_x4(bl + 4, aB1 + kl * 2);
            #pragma unroll
            for (int ms = 0; ms < 2; ms++)
                #pragma unroll
                for (int nt = 0; nt < 4; nt++)
                    mma16816(&c[(ms * 4 + nt) * 4], &ah[ms * 4], &bh[nt * 2]);
            #pragma unroll
            for (int ms = 0; ms < 2; ms++)
                #pragma unroll
                for (int nt = 0; nt < 4; nt++)
                    mma16816(&c[(ms * 4 + nt) * 4], &ah[ms * 4], &bl[nt * 2]);
            ldm_x4(al,     aA0 + kl * 2);
            ldm_x4(al + 4, aA1 + kl * 2);
            #pragma unroll
            for (int ms = 0; ms < 2; ms++)
                #pragma unroll
                for (int nt = 0; nt < 4; nt++)
                    mma16816(&c[(ms * 4 + nt) * 4], &al[ms * 4], &bh[nt * 2]);
        }
        __syncthreads();   // all ldmatrix reads of Z complete before overwrite

        // epilogue: stage cost (x_t), x_{t+1} = x_t + dt*tanh(y_t), pack Dx
        const bool wrz = (t < H_DIM - 1);
        #pragma unroll
        for (int ms = 0; ms < 2; ms++)
            #pragma unroll
            for (int nt = 0; nt < 4; nt++)
                #pragma unroll
                for (int h = 0; h < 2; h++) {
                    const int i0 = (ms * 4 + nt) * 4 + h * 2;
                    float x0v = xr[i0], x1v = xr[i0 + 1];
                    win[ms * 2 + h] += x0v * x0v + x1v * x1v;
                    float d0 = DT_F * tanh_fast(c[i0]);
                    float d1 = DT_F * tanh_fast(c[i0 + 1]);
                    xr[i0] = x0v + d0;
                    xr[i0 + 1] = x1v + d1;
                    if (wrz) {
                        int row = m0 + ms * 16 + h * 8 + (lane >> 2);
                        int wcol = (n0 >> 1) + nt * 4 + (lane & 3);
                        Zw[row * LDWW + wcol]      = hi2(d0, d1);
                        Zw[row * LDWW + 64 + wcol] = lo2(d0, d1);
                    }
                }

        if (wrz) {   // u_{t+1}, Du packing
            float4 f0 = *(const float4*)(up + (size_t)(t + 1) * C_DIM);
            float4 f1 = *(const float4*)(up + (size_t)(t + 1) * C_DIM + 4);
            float uv[8] = {f0.x, f0.y, f0.z, f0.w, f1.x, f1.y, f1.z, f1.w};
            const float* pp = prev + (t + 1) * C_DIM + uq * 8;
            float du[8];
            #pragma unroll
            for (int e = 0; e < 8; e++) {
                float u = uv[e] + (inh ? pp[e] : 0.f);
                u = fminf(fmaxf(u, -2.f), 2.f);
                ucost += u * u;
                du[e] = u - uold[e];
                uold[e] = u;
            }
            int bh_ = us * LDWW + 128 + uq * 4;
            #pragma unroll
            for (int e = 0; e < 8; e += 2) {
                Zw[bh_ + (e >> 1)]      = hi2(du[e], du[e + 1]);
                Zw[bh_ + 16 + (e >> 1)] = lo2(du[e], du[e + 1]);
            }
        }

        if ((t & 7) == 7) {   // flush fp32 cost window into fp64
            #pragma unroll
            for (int i = 0; i < 4; i++) { s_cd[tid][i] += (double)win[i]; win[i] = 0.f; }
        }
        __syncthreads();   // Z writes visible for next step's mma
    }

    // terminal ||x_H||^2 + final flush
    #pragma unroll
    for (int ms = 0; ms < 2; ms++)
        #pragma unroll
        for (int nt = 0; nt < 4; nt++)
            #pragma unroll
            for (int h = 0; h < 2; h++) {
                const int i0 = (ms * 4 + nt) * 4 + h * 2;
                win[ms * 2 + h] += xr[i0] * xr[i0] + xr[i0 + 1] * xr[i0 + 1];
            }
    #pragma unroll
    for (int i = 0; i < 4; i++) s_cd[tid][i] += (double)win[i];
    s_uc[uq][us] = ucost;
    __syncthreads();

    // per-sample cost assembly
    if (tid < MB) {
        const int s = tid;
        const int stIdx = ((s >> 4) & 1) * 2 + ((s >> 3) & 1);
        const int baseT = (s >> 5) * 128 + (s & 7) * 4;
        double cs = 0.0;
        #pragma unroll
        for (int wn = 0; wn < 4; wn++)
            #pragma unroll
            for (int b = 0; b < 4; b++)
                cs += s_cd[baseT + wn * 32 + b][stIdx];
        double uu = (double)s_uc[0][s] + s_uc[1][s] + s_uc[2][s] + s_uc[3][s];
        g_costs[n0g + s] = cs + 0.1 * uu;
    }
}

// ---------------------------------------------------------------------------
// K2: softmax over -costs (single block, fp64).
// ---------------------------------------------------------------------------
__global__ void k_softmax(int N)
{
    __shared__ double sm[1024];
    const int tid = threadIdx.x;
    double lmin = 1e300;
    for (int n = tid; n < N; n += 1024) lmin = fmin(lmin, g_costs[n]);
    sm[tid] = lmin; __syncthreads();
    for (int s = 512; s > 0; s >>= 1) {
        if (tid < s) sm[tid] = fmin(sm[tid], sm[tid + s]);
        __syncthreads();
    }
    double cmin = sm[0];
    __syncthreads();
    double ls = 0.0;
    for (int n = tid; n < N; n += 1024) {
        double w = exp(cmin - g_costs[n]);
        g_wtmp[n] = w; ls += w;
    }
    sm[tid] = ls; __syncthreads();
    for (int s = 512; s > 0; s >>= 1) {
        if (tid < s) sm[tid] += sm[tid + s];
        __syncthreads();
    }
    double inv = 1.0 / sm[0];
    for (int n = tid; n < N; n += 1024)
        g_weights[n] = (float)(g_wtmp[n] * inv);
}

// ---------------------------------------------------------------------------
// K3: partial weighted action sum with negligible-weight skip.
// ---------------------------------------------------------------------------
__global__ void k_wsum(const float* __restrict__ noises,
                       const float* __restrict__ prev, int thr, int N)
{
    const int ch = blockIdx.x, h = blockIdx.y;
    const int cc = threadIdx.x & 31, r = threadIdx.x >> 5;
    const int cnt = N / NCHUNK;
    const int n0 = ch * cnt;
    const float pv = prev[h * C_DIM + cc];
    double acc = 0.0;
    for (int nn = n0 + r; nn < n0 + cnt; nn += 8) {
        float w = g_weights[nn];
        if (w > 1e-12f) {
            float v = noises[((size_t)nn * H_DIM + h) * C_DIM + cc];
            if (nn < thr) v += pv;
            v = fminf(fmaxf(v, -2.f), 2.f);
            acc += (double)w * (double)v;
        }
    }
    __shared__ double s[8][33];
    s[r][cc] = acc; __syncthreads();
    if (r == 0) {
        double t = 0.0;
        #pragma unroll
        for (int i = 0; i < 8; i++) t += s[i][cc];
        g_part[(ch * H_DIM + h) * C_DIM + cc] = t;
    }
}

__global__ void k_afinal(float* __restrict__ outA)
{
    int idx = blockIdx.x * 1024 + threadIdx.x;
    if (idx >= H_DIM * C_DIM) return;
    double t = 0.0;
    #pragma unroll
    for (int ch = 0; ch < NCHUNK; ch++) t += g_part[ch * H_DIM * C_DIM + idx];
    outA[idx] = (float)t;
}

// ---------------------------------------------------------------------------
// K5: fp32 rollout of the optimal action sequence (single block).
// ---------------------------------------------------------------------------
__global__ __launch_bounds__(256, 1)
void k_opt(const float* __restrict__ state, const float* __restrict__ A,
           const float* __restrict__ Bm, const float* __restrict__ outA,
           float* __restrict__ outS)
{
    extern __shared__ float Ws[];     // [160][WPAD]
    __shared__ float xu[160];
    __shared__ float part[S_DIM];
    const int tid = threadIdx.x;
    const int s = tid & 127, half = tid >> 7;

    for (int idx = tid; idx < 160 * S_DIM; idx += 256) {
        int ss = idx / 160, k = idx - ss * 160;
        Ws[k * WPAD + ss] = (k < S_DIM) ? A[ss * S_DIM + k]
                                        : Bm[ss * C_DIM + (k - S_DIM)];
    }
    if (tid < S_DIM) {
        float x0 = state[tid];
        xu[tid] = x0;
        outS[tid] = x0;
    }
    for (int t = 0; t < H_DIM; t++) {
        if (tid < C_DIM) xu[S_DIM + tid] = outA[t * C_DIM + tid];
        __syncthreads();
        float acc = 0.f;
        const int k0 = half * 80;
        #pragma unroll 8
        for (int k = k0; k < k0 + 80; k++)
            acc = fmaf(xu[k], Ws[k * WPAD + s], acc);
        if (half) part[s] = acc;
        __syncthreads();
        if (!half) {
            float y = acc + part[s];
            float xn = xu[s] + DT_F * tanh_fast(y);
            xu[s] = xn;
            outS[(t + 1) * S_DIM + s] = xn;
        }
        __syncthreads();
    }
}

// ---------------------------------------------------------------------------
extern "C" void kernel_launch(void* const* d_in, const int* in_sizes, int n_in,
                              void* d_out, int out_size)
{
    const float* state  = (const float*)d_in[0];
    const float* A      = (const float*)d_in[1];
    const float* Bm     = (const float*)d_in[2];
    const float* noises = (const float*)d_in[3];
    const float* prev   = (const float*)d_in[4];

    int N = in_sizes[3] / (H_DIM * C_DIM);
    if (N > NMAX) N = NMAX;
    int thr = (int)((double)N * (1.0 - 0.2));

    float* outA = (float*)d_out;
    float* outS = outA + H_DIM * C_DIM;

    const int smem1 = 2 * MB * LDW * 2 + 1024;             // 168,960
    const int smem5 = 160 * WPAD * (int)sizeof(float);     // 84,480
    cudaFuncSetAttribute(k_roll, cudaFuncAttributeMaxDynamicSharedMemorySize, smem1);
    cudaFuncSetAttribute(k_opt,  cudaFuncAttributeMaxDynamicSharedMemorySize, smem5);

    k_roll<<<N / MB, 512, smem1>>>(state, A, Bm, noises, prev, thr);
    k_softmax<<<1, 1024>>>(N);
    dim3 g3(NCHUNK, H_DIM);
    k_wsum<<<g3, 256>>>(noises, prev, thr, N);
    k_afinal<<<2, 1024>>>(outA);
    k_opt<<<1, 256, smem5>>>(state, A, Bm, outA, outS);
}

// round 6
// speedup vs baseline: 2.2020x; 1.1035x over previous
#include <cuda_runtime.h>
#include <cuda_bf16.h>
#include <math.h>
#include <stdint.h>

// ---------------------------------------------------------------------------
// MPPI, N=16384 H=64 S=128 C=32, via incremental split-bf16 mma.sync rollouts.
// y (=x@A^T+u@B^T) lives in fp32 mma accumulators across steps; each step adds
// dY = Dx@A^T + Du@B^T with Dx,Du in bf16 hi+lo (3 cross terms, lo*lo dropped).
// R6: CTA-wide __syncthreads in the step loop replaced by per-m-group named
// barriers (all Z-row dependencies are m-group-local), u loads prefetched.
// ---------------------------------------------------------------------------

#define S_DIM 128
#define C_DIM 32
#define H_DIM 64
#define DT_F  0.05f
#define NMAX  16384
#define NCHUNK 32
#define MB    128
#define LDW   328        // bf16 elements per Z/W SMEM row (320 used + 8 pad)
#define LDWW  164        // 32-bit words per row
#define WPAD  132

__device__ double g_costs[NMAX];
__device__ double g_wtmp[NMAX];
__device__ float  g_weights[NMAX];
__device__ double g_part[NCHUNK * H_DIM * C_DIM];

// ---------------------------- helpers --------------------------------------
__device__ __forceinline__ uint32_t smem_u32(const void* p) {
    uint32_t a;
    asm("{ .reg .u64 t; cvta.to.shared.u64 t, %1; cvt.u32.u64 %0, t; }"
        : "=r"(a) : "l"(p));
    return a;
}
__device__ __forceinline__ void bar_grp(int id) {
    asm volatile("bar.sync %0, 128;" :: "r"(id) : "memory");
}
__device__ __forceinline__ void ldm_x4(uint32_t* r, uint32_t addr) {
    asm volatile("ldmatrix.sync.aligned.m8n8.x4.shared.b16 {%0,%1,%2,%3}, [%4];"
                 : "=r"(r[0]), "=r"(r[1]), "=r"(r[2]), "=r"(r[3]) : "r"(addr));
}
__device__ __forceinline__ void mma16816(float* c, const uint32_t* a, const uint32_t* b) {
    asm volatile(
        "mma.sync.aligned.m16n8k16.row.col.f32.bf16.bf16.f32 "
        "{%0,%1,%2,%3}, {%4,%5,%6,%7}, {%8,%9}, {%0,%1,%2,%3};"
        : "+f"(c[0]), "+f"(c[1]), "+f"(c[2]), "+f"(c[3])
        : "r"(a[0]), "r"(a[1]), "r"(a[2]), "r"(a[3]), "r"(b[0]), "r"(b[1]));
}
// pack 2 floats -> bf16x2: hi = truncated upper halves
__device__ __forceinline__ uint32_t hi2(float a, float b) {
    uint32_t r;
    asm("prmt.b32 %0, %1, %2, 0x7632;"
        : "=r"(r) : "r"(__float_as_uint(a)), "r"(__float_as_uint(b)));
    return r;
}
__device__ __forceinline__ float trunc16(float v) {
    return __uint_as_float(__float_as_uint(v) & 0xFFFF0000u);
}
__device__ __forceinline__ uint32_t lo2(float a, float b) {
    float la = a - trunc16(a), lb = b - trunc16(b);
    uint32_t r;
    asm("cvt.rn.bf16x2.f32 %0, %1, %2;" : "=r"(r) : "f"(lb), "f"(la));
    return r;
}
__device__ __forceinline__ float tanh_fast(float x) {
    float xc = fminf(fmaxf(x, -15.f), 15.f);
    float e, r;
    asm("ex2.approx.f32 %0, %1;" : "=f"(e) : "f"(xc * 2.885390081777927f));
    asm("rcp.approx.f32 %0, %1;" : "=f"(r) : "f"(e + 1.0f));
    return fmaf(-2.0f, r, 1.0f);
}
__device__ __forceinline__ unsigned short hi1(float v) {
    return (unsigned short)(__float_as_uint(v) >> 16);
}
__device__ __forceinline__ unsigned short lo1(float v) {
    __nv_bfloat16 b = __float2bfloat16(v - trunc16(v));
    return *(unsigned short*)&b;
}

// ---------------------------------------------------------------------------
// K1: rollout.  512 threads = 16 warps (4 m-groups x 4 n-groups of 32x32),
// 128 samples per CTA, grid = 128.
// K layout of Z rows / W rows: [Dxh 0..127 | Dxl 128..255 | Duh 256..287 | Dul 288..319]
// ---------------------------------------------------------------------------
__global__ __launch_bounds__(512, 1)
void k_roll(const float* __restrict__ state, const float* __restrict__ A,
            const float* __restrict__ Bm, const float* __restrict__ noises,
            const float* __restrict__ prev, int thr)
{
    extern __shared__ char dynsm[];
    char* zc = (char*)(((uintptr_t)dynsm + 1023) & ~(uintptr_t)1023);
    char* wc = zc + MB * LDW * 2;
    unsigned short* Zh16 = (unsigned short*)zc;
    unsigned short* Wh16 = (unsigned short*)wc;
    uint32_t* Zw = (uint32_t*)zc;
    const uint32_t zb = smem_u32(zc), wb = smem_u32(wc);

    __shared__ double s_cd[512][4];
    __shared__ float  s_uc[4][128];

    const int tid  = threadIdx.x;
    const int wid  = tid >> 5, lane = tid & 31;
    const int mg   = wid >> 2;               // m-group 0..3 (barrier scope)
    const int m0   = mg * 32, n0 = (wid & 3) * 32;
    const int n0g  = blockIdx.x * MB;
    const int barid = 1 + mg;                // named barriers 1..4

    // ldmatrix lane base addresses (A: rows m, B: rows n), byte units
    const uint32_t aA0 = zb + (uint32_t)(m0 + (lane & 15)) * (LDW * 2) + (lane >> 4) * 16;
    const uint32_t aA1 = aA0 + 16 * LDW * 2;
    const uint32_t aB0 = wb + (uint32_t)(n0 + (lane & 7) + ((lane >> 4) & 1) * 8) * (LDW * 2)
                            + ((lane >> 3) & 1) * 16;
    const uint32_t aB1 = aB0 + 16 * LDW * 2;

    // ---- preamble ----
    #pragma unroll
    for (int i = 0; i < 4; i++) s_cd[tid][i] = 0.0;

    for (int idx = tid; idx < S_DIM * S_DIM; idx += 512) {   // W <- A
        int n = idx >> 7, k = idx & 127;
        float v = A[idx];
        Wh16[n * LDW + k]       = hi1(v);
        Wh16[n * LDW + 128 + k] = lo1(v);
    }
    for (int idx = tid; idx < S_DIM * C_DIM; idx += 512) {   // W <- B
        int n = idx >> 5, cch = idx & 31;
        float v = Bm[idx];
        Wh16[n * LDW + 256 + cch] = hi1(v);
        Wh16[n * LDW + 288 + cch] = lo1(v);
    }
    for (int idx = tid; idx < MB * S_DIM; idx += 512) {      // Z <- x0 (Dx at t=0)
        int mm = idx >> 7, k = idx & 127;
        float v = state[k];
        Zh16[mm * LDW + k]       = hi1(v);
        Zh16[mm * LDW + 128 + k] = lo1(v);
    }

    // u role: sample us, channels uq*8..uq*8+7  (us is in m-group tid>>7 == mg)
    const int us = tid >> 2, uq = tid & 3;
    const bool inh = (n0g + us) < thr;
    const float* up = noises + (size_t)(n0g + us) * (H_DIM * C_DIM) + uq * 8;
    float uold[8];
    float ucost = 0.f;
    {
        float4 f0 = *(const float4*)(up);
        float4 f1 = *(const float4*)(up + 4);
        float uv[8] = {f0.x, f0.y, f0.z, f0.w, f1.x, f1.y, f1.z, f1.w};
        const float* pp = prev + uq * 8;
        #pragma unroll
        for (int e = 0; e < 8; e++) {
            float u = uv[e] + (inh ? pp[e] : 0.f);
            u = fminf(fmaxf(u, -2.f), 2.f);
            ucost += u * u;
            uold[e] = u;
        }
        int bh_ = us * LDWW + 128 + uq * 4;
        #pragma unroll
        for (int e = 0; e < 8; e += 2) {
            Zw[bh_ + (e >> 1)]      = hi2(uold[e], uold[e + 1]);   // Duh
            Zw[bh_ + 16 + (e >> 1)] = lo2(uold[e], uold[e + 1]);   // Dul
        }
    }

    // x registers aligned with C-fragment cells: idx (ms*4+nt)*4 + j
    float c[32], xr[32];
    #pragma unroll
    for (int ms = 0; ms < 2; ms++)
        #pragma unroll
        for (int nt = 0; nt < 4; nt++)
            #pragma unroll
            for (int j = 0; j < 4; j++) {
                int col = n0 + nt * 8 + (lane & 3) * 2 + (j & 1);
                xr[(ms * 4 + nt) * 4 + j] = state[col];
                c[(ms * 4 + nt) * 4 + j] = 0.f;
            }

    float win[4] = {0.f, 0.f, 0.f, 0.f};
    __syncthreads();   // preamble visible to all groups (W is read cross-group)

    // ---- main loop: per-m-group synchronization only ----
    #pragma unroll 1
    for (int t = 0; t < H_DIM; t++) {
        const bool wrz = (t < H_DIM - 1);
        float4 f0, f1;
        if (wrz) {   // prefetch u_{t+1}; latency hides under the mma phase
            f0 = *(const float4*)(up + (size_t)(t + 1) * C_DIM);
            f1 = *(const float4*)(up + (size_t)(t + 1) * C_DIM + 4);
        }

        // mma phase: C += Dx@A^T + Du@B^T  (3 split terms)
        #pragma unroll
        for (int ch = 0; ch < 10; ch++) {
            const int kh = (ch < 8) ? ch * 16 : (256 + (ch - 8) * 16);
            const int kl = kh + ((ch < 8) ? 128 : 32);
            uint32_t ah[8], al[8], bh[8], bl[8];
            ldm_x4(ah,     aA0 + kh * 2);
            ldm_x4(ah + 4, aA1 + kh * 2);
            ldm_x4(bh,     aB0 + kh * 2);
            ldm_x4(bh + 4, aB1 + kh * 2);
            ldm_x4(bl,     aB0 + kl * 2);
            ldm_x4(bl + 4, aB1 + kl * 2);
            #pragma unroll
            for (int ms = 0; ms < 2; ms++)
                #pragma unroll
                for (int nt = 0; nt < 4; nt++)
                    mma16816(&c[(ms * 4 + nt) * 4], &ah[ms * 4], &bh[nt * 2]);
            #pragma unroll
            for (int ms = 0; ms < 2; ms++)
                #pragma unroll
                for (int nt = 0; nt < 4; nt++)
                    mma16816(&c[(ms * 4 + nt) * 4], &ah[ms * 4], &bl[nt * 2]);
            ldm_x4(al,     aA0 + kl * 2);
            ldm_x4(al + 4, aA1 + kl * 2);
            #pragma unroll
            for (int ms = 0; ms < 2; ms++)
                #pragma unroll
                for (int nt = 0; nt < 4; nt++)
                    mma16816(&c[(ms * 4 + nt) * 4], &al[ms * 4], &bh[nt * 2]);
        }
        bar_grp(barid);   // group's ldmatrix reads of Z rows m0..m0+31 done

        // epilogue: stage cost (x_t), x_{t+1} = x_t + dt*tanh(y_t), pack Dx
        #pragma unroll
        for (int ms = 0; ms < 2; ms++)
            #pragma unroll
            for (int nt = 0; nt < 4; nt++)
                #pragma unroll
                for (int h = 0; h < 2; h++) {
                    const int i0 = (ms * 4 + nt) * 4 + h * 2;
                    float x0v = xr[i0], x1v = xr[i0 + 1];
                    win[ms * 2 + h] += x0v * x0v + x1v * x1v;
                    float d0 = DT_F * tanh_fast(c[i0]);
                    float d1 = DT_F * tanh_fast(c[i0 + 1]);
                    xr[i0] = x0v + d0;
                    xr[i0 + 1] = x1v + d1;
                    if (wrz) {
                        int row = m0 + ms * 16 + h * 8 + (lane >> 2);
                        int wcol = (n0 >> 1) + nt * 4 + (lane & 3);
                        Zw[row * LDWW + wcol]      = hi2(d0, d1);
                        Zw[row * LDWW + 64 + wcol] = lo2(d0, d1);
                    }
                }

        if (wrz) {   // u_{t+1} (prefetched), Du packing — same m-group rows
            float uv[8] = {f0.x, f0.y, f0.z, f0.w, f1.x, f1.y, f1.z, f1.w};
            const float* pp = prev + (t + 1) * C_DIM + uq * 8;
            float du[8];
            #pragma unroll
            for (int e = 0; e < 8; e++) {
                float u = uv[e] + (inh ? pp[e] : 0.f);
                u = fminf(fmaxf(u, -2.f), 2.f);
                ucost += u * u;
                du[e] = u - uold[e];
                uold[e] = u;
            }
            int bh_ = us * LDWW + 128 + uq * 4;
            #pragma unroll
            for (int e = 0; e < 8; e += 2) {
                Zw[bh_ + (e >> 1)]      = hi2(du[e], du[e + 1]);
                Zw[bh_ + 16 + (e >> 1)] = lo2(du[e], du[e + 1]);
            }
        }

        if ((t & 7) == 7) {   // flush fp32 cost window into fp64
            #pragma unroll
            for (int i = 0; i < 4; i++) { s_cd[tid][i] += (double)win[i]; win[i] = 0.f; }
        }
        bar_grp(barid);   // group's Z writes visible for its next mma phase
    }

    // terminal ||x_H||^2 + final flush
    #pragma unroll
    for (int ms = 0; ms < 2; ms++)
        #pragma unroll
        for (int nt = 0; nt < 4; nt++)
            #pragma unroll
            for (int h = 0; h < 2; h++) {
                const int i0 = (ms * 4 + nt) * 4 + h * 2;
                win[ms * 2 + h] += xr[i0] * xr[i0] + xr[i0 + 1] * xr[i0 + 1];
            }
    #pragma unroll
    for (int i = 0; i < 4; i++) s_cd[tid][i] += (double)win[i];
    s_uc[uq][us] = ucost;
    __syncthreads();

    // per-sample cost assembly
    if (tid < MB) {
        const int s = tid;
        const int stIdx = ((s >> 4) & 1) * 2 + ((s >> 3) & 1);
        const int baseT = (s >> 5) * 128 + (s & 7) * 4;
        double cs = 0.0;
        #pragma unroll
        for (int wn = 0; wn < 4; wn++)
            #pragma unroll
            for (int b = 0; b < 4; b++)
                cs += s_cd[baseT + wn * 32 + b][stIdx];
        double uu = (double)s_uc[0][s] + s_uc[1][s] + s_uc[2][s] + s_uc[3][s];
        g_costs[n0g + s] = cs + 0.1 * uu;
    }
}

// ---------------------------------------------------------------------------
// K2: softmax over -costs (single block, fp64).
// ---------------------------------------------------------------------------
__global__ void k_softmax(int N)
{
    __shared__ double sm[1024];
    const int tid = threadIdx.x;
    double lmin = 1e300;
    for (int n = tid; n < N; n += 1024) lmin = fmin(lmin, g_costs[n]);
    sm[tid] = lmin; __syncthreads();
    for (int s = 512; s > 0; s >>= 1) {
        if (tid < s) sm[tid] = fmin(sm[tid], sm[tid + s]);
        __syncthreads();
    }
    double cmin = sm[0];
    __syncthreads();
    double ls = 0.0;
    for (int n = tid; n < N; n += 1024) {
        double w = exp(cmin - g_costs[n]);
        g_wtmp[n] = w; ls += w;
    }
    sm[tid] = ls; __syncthreads();
    for (int s = 512; s > 0; s >>= 1) {
        if (tid < s) sm[tid] += sm[tid + s];
        __syncthreads();
    }
    double inv = 1.0 / sm[0];
    for (int n = tid; n < N; n += 1024)
        g_weights[n] = (float)(g_wtmp[n] * inv);
}

// ---------------------------------------------------------------------------
// K3: partial weighted action sum with negligible-weight skip.
// ---------------------------------------------------------------------------
__global__ void k_wsum(const float* __restrict__ noises,
                       const float* __restrict__ prev, int thr, int N)
{
    const int ch = blockIdx.x, h = blockIdx.y;
    const int cc = threadIdx.x & 31, r = threadIdx.x >> 5;
    const int cnt = N / NCHUNK;
    const int n0 = ch * cnt;
    const float pv = prev[h * C_DIM + cc];
    double acc = 0.0;
    for (int nn = n0 + r; nn < n0 + cnt; nn += 8) {
        float w = g_weights[nn];
        if (w > 1e-12f) {
            float v = noises[((size_t)nn * H_DIM + h) * C_DIM + cc];
            if (nn < thr) v += pv;
            v = fminf(fmaxf(v, -2.f), 2.f);
            acc += (double)w * (double)v;
        }
    }
    __shared__ double s[8][33];
    s[r][cc] = acc; __syncthreads();
    if (r == 0) {
        double t = 0.0;
        #pragma unroll
        for (int i = 0; i < 8; i++) t += s[i][cc];
        g_part[(ch * H_DIM + h) * C_DIM + cc] = t;
    }
}

__global__ void k_afinal(float* __restrict__ outA)
{
    int idx = blockIdx.x * 1024 + threadIdx.x;
    if (idx >= H_DIM * C_DIM) return;
    double t = 0.0;
    #pragma unroll
    for (int ch = 0; ch < NCHUNK; ch++) t += g_part[ch * H_DIM * C_DIM + idx];
    outA[idx] = (float)t;
}

// ---------------------------------------------------------------------------
// K5: fp32 rollout of the optimal action sequence (single block).
// ---------------------------------------------------------------------------
__global__ __launch_bounds__(256, 1)
void k_opt(const float* __restrict__ state, const float* __restrict__ A,
           const float* __restrict__ Bm, const float* __restrict__ outA,
           float* __restrict__ outS)
{
    extern __shared__ float Ws[];     // [160][WPAD]
    __shared__ float xu[160];
    __shared__ float part[S_DIM];
    const int tid = threadIdx.x;
    const int s = tid & 127, half = tid >> 7;

    for (int idx = tid; idx < 160 * S_DIM; idx += 256) {
        int ss = idx / 160, k = idx - ss * 160;
        Ws[k * WPAD + ss] = (k < S_DIM) ? A[ss * S_DIM + k]
                                        : Bm[ss * C_DIM + (k - S_DIM)];
    }
    if (tid < S_DIM) {
        float x0 = state[tid];
        xu[tid] = x0;
        outS[tid] = x0;
    }
    for (int t = 0; t < H_DIM; t++) {
        if (tid < C_DIM) xu[S_DIM + tid] = outA[t * C_DIM + tid];
        __syncthreads();
        float acc = 0.f;
        const int k0 = half * 80;
        #pragma unroll 8
        for (int k = k0; k < k0 + 80; k++)
            acc = fmaf(xu[k], Ws[k * WPAD + s], acc);
        if (half) part[s] = acc;
        __syncthreads();
        if (!half) {
            float y = acc + part[s];
            float xn = xu[s] + DT_F * tanh_fast(y);
            xu[s] = xn;
            outS[(t + 1) * S_DIM + s] = xn;
        }
        __syncthreads();
    }
}

// ---------------------------------------------------------------------------
extern "C" void kernel_launch(void* const* d_in, const int* in_sizes, int n_in,
                              void* d_out, int out_size)
{
    const float* state  = (const float*)d_in[0];
    const float* A      = (const float*)d_in[1];
    const float* Bm     = (const float*)d_in[2];
    const float* noises = (const float*)d_in[3];
    const float* prev   = (const float*)d_in[4];

    int N = in_sizes[3] / (H_DIM * C_DIM);
    if (N > NMAX) N = NMAX;
    int thr = (int)((double)N * (1.0 - 0.2));

    float* outA = (float*)d_out;
    float* outS = outA + H_DIM * C_DIM;

    const int smem1 = 2 * MB * LDW * 2 + 1024;             // 168,960
    const int smem5 = 160 * WPAD * (int)sizeof(float);     // 84,480
    cudaFuncSetAttribute(k_roll, cudaFuncAttributeMaxDynamicSharedMemorySize, smem1);
    cudaFuncSetAttribute(k_opt,  cudaFuncAttributeMaxDynamicSharedMemorySize, smem5);

    k_roll<<<N / MB, 512, smem1>>>(state, A, Bm, noises, prev, thr);
    k_softmax<<<1, 1024>>>(N);
    dim3 g3(NCHUNK, H_DIM);
    k_wsum<<<g3, 256>>>(noises, prev, thr, N);
    k_afinal<<<2, 1024>>>(outA);
    k_opt<<<1, 256, smem5>>>(state, A, Bm, outA, outS);
}

// round 7
// speedup vs baseline: 2.7154x; 1.2331x over previous
#include <cuda_runtime.h>
#include <cuda_fp16.h>
#include <math.h>
#include <stdint.h>

// ---------------------------------------------------------------------------
// MPPI, N=16384 H=64 S=128 C=32, incremental fp16 mma.sync rollouts.
// y accumulates in fp32 mma C-fragments across steps; per step add
// dY = Dx@[Ah|Al]^T + Du@[Bh|Bl]^T with fp16 EXACT products (W split hi/lo,
// Dx single fp16, Du single fp16 with error feedback).  x0/u0 injected via
// two hi/lo mma passes before the loop.
// ---------------------------------------------------------------------------

#define S_DIM 128
#define C_DIM 32
#define H_DIM 64
#define DT_F  0.05f
#define NMAX  16384
#define NCHUNK 32
#define MB    128
#define LDZ   168        // halfs per Z row (160 used + 8 pad) -> 336B, odd*16B
#define LDZW  84         // words per Z row
#define ZBYTES (128 * LDZ * 2)   // 43008 per buffer
#define LDW   328        // halfs per W row (320 used + 8 pad) -> 656B, odd*16B
#define WPAD  132

__device__ double g_costs[NMAX];
__device__ double g_wtmp[NMAX];
__device__ float  g_weights[NMAX];
__device__ double g_part[NCHUNK * H_DIM * C_DIM];

// ---------------------------- helpers --------------------------------------
__device__ __forceinline__ uint32_t smem_u32(const void* p) {
    uint32_t a;
    asm("{ .reg .u64 t; cvta.to.shared.u64 t, %1; cvt.u32.u64 %0, t; }"
        : "=r"(a) : "l"(p));
    return a;
}
__device__ __forceinline__ void bar_grp(int id) {
    asm volatile("bar.sync %0, 128;" :: "r"(id) : "memory");
}
__device__ __forceinline__ void ldm_x4(uint32_t* r, uint32_t addr) {
    asm volatile("ldmatrix.sync.aligned.m8n8.x4.shared.b16 {%0,%1,%2,%3}, [%4];"
                 : "=r"(r[0]), "=r"(r[1]), "=r"(r[2]), "=r"(r[3]) : "r"(addr));
}
__device__ __forceinline__ void mma16816(float* c, const uint32_t* a, const uint32_t* b) {
    asm volatile(
        "mma.sync.aligned.m16n8k16.row.col.f32.f16.f16.f32 "
        "{%0,%1,%2,%3}, {%4,%5,%6,%7}, {%8,%9}, {%0,%1,%2,%3};"
        : "+f"(c[0]), "+f"(c[1]), "+f"(c[2]), "+f"(c[3])
        : "r"(a[0]), "r"(a[1]), "r"(a[2]), "r"(a[3]), "r"(b[0]), "r"(b[1]));
}
__device__ __forceinline__ uint32_t pkh2(float a, float b) {
    __half2 h = __floats2half2_rn(a, b);
    return *(uint32_t*)&h;
}
__device__ __forceinline__ float tanh_fast(float x) {
    float xc = fminf(fmaxf(x, -15.f), 15.f);
    float e, r;
    asm("ex2.approx.f32 %0, %1;" : "=f"(e) : "f"(xc * 2.885390081777927f));
    asm("rcp.approx.f32 %0, %1;" : "=f"(r) : "f"(e + 1.0f));
    return fmaf(-2.0f, r, 1.0f);
}

// ---------------------------------------------------------------------------
// K1: rollout.  512 threads = 16 warps (4 m-groups x 4 n-groups of 32x32),
// 128 samples per CTA, grid = 128.
// W K-cols: [Ah 0..127 | Bh 128..159 | Al 160..287 | Bl 288..319]
// Z K-cols: [Dx 0..127 | Du 128..159]  (double-buffered)
// chunk ch 0..9: A = Z[16ch..+16); B1 = W[16ch..+16); B2 = W[160+16ch..+16)
// ---------------------------------------------------------------------------
__global__ __launch_bounds__(512, 1)
void k_roll(const float* __restrict__ state, const float* __restrict__ A,
            const float* __restrict__ Bm, const float* __restrict__ noises,
            const float* __restrict__ prev, int thr)
{
    extern __shared__ char dynsm[];
    char* zc = (char*)(((uintptr_t)dynsm + 1023) & ~(uintptr_t)1023);
    char* wc = zc + 2 * ZBYTES;
    __half* Zh = (__half*)zc;                  // [2][128][LDZ]
    __half* Wh = (__half*)wc;                  // [128][LDW]
    uint32_t* Zw = (uint32_t*)zc;
    const uint32_t zb = smem_u32(zc), wb = smem_u32(wc);

    __shared__ double s_cd[512][4];
    __shared__ float  s_uc[4][128];

    const int tid  = threadIdx.x;
    const int wid  = tid >> 5, lane = tid & 31;
    const int mg   = wid >> 2;
    const int m0   = mg * 32, n0 = (wid & 3) * 32;
    const int n0g  = blockIdx.x * MB;
    const int barid = 1 + mg;

    // ldmatrix lane bases (A rows m from Z; B rows n from W)
    const uint32_t aA0b = zb + (uint32_t)(m0 + (lane & 15)) * (LDZ * 2) + (lane >> 4) * 16;
    const uint32_t aB0  = wb + (uint32_t)(n0 + (lane & 7) + ((lane >> 4) & 1) * 8) * (LDW * 2)
                             + ((lane >> 3) & 1) * 16;
    const uint32_t aB1  = aB0 + 16 * LDW * 2;

    // ---- preamble ----
    #pragma unroll
    for (int i = 0; i < 4; i++) s_cd[tid][i] = 0.0;

    for (int idx = tid; idx < S_DIM * S_DIM; idx += 512) {   // W <- A hi/lo
        int n = idx >> 7, k = idx & 127;
        float v = A[idx];
        __half h = __float2half_rn(v);
        __half l = __float2half_rn(v - __half2float(h));
        Wh[n * LDW + k]       = h;
        Wh[n * LDW + 160 + k] = l;
    }
    for (int idx = tid; idx < S_DIM * C_DIM; idx += 512) {   // W <- B hi/lo
        int n = idx >> 5, cch = idx & 31;
        float v = Bm[idx];
        __half h = __float2half_rn(v);
        __half l = __float2half_rn(v - __half2float(h));
        Wh[n * LDW + 128 + cch] = h;
        Wh[n * LDW + 288 + cch] = l;
    }
    for (int idx = tid; idx < MB * S_DIM; idx += 512) {      // Z0 <- x0h, Z1 <- x0l
        int mm = idx >> 7, k = idx & 127;
        float v = state[k];
        __half h = __float2half_rn(v);
        __half l = __float2half_rn(v - __half2float(h));
        Zh[mm * LDZ + k]                 = h;
        Zh[ZBYTES / 2 + mm * LDZ + k]    = l;
    }

    // u role: sample us, channels uq*8..uq*8+7 (us in m-group tid>>7 == mg)
    const int us = tid >> 2, uq = tid & 3;
    const bool inh = (n0g + us) < thr;
    const float* up = noises + (size_t)(n0g + us) * (H_DIM * C_DIM) + uq * 8;
    float uold[8], ru[8];
    float ucost = 0.f;
    {
        float4 f0 = *(const float4*)(up);
        float4 f1 = *(const float4*)(up + 4);
        float uv[8] = {f0.x, f0.y, f0.z, f0.w, f1.x, f1.y, f1.z, f1.w};
        const float* pp = prev + uq * 8;
        #pragma unroll
        for (int e = 0; e < 8; e++) {
            float u = uv[e] + (inh ? pp[e] : 0.f);
            u = fminf(fmaxf(u, -2.f), 2.f);
            ucost += u * u;
            uold[e] = u;
            __half h = __float2half_rn(u);
            float  rh = u - __half2float(h);
            __half l = __float2half_rn(rh);
            ru[e] = rh - __half2float(l);
            Zh[us * LDZ + 128 + uq * 8 + e]              = h;   // u0h
            Zh[ZBYTES / 2 + us * LDZ + 128 + uq * 8 + e] = l;   // u0l
        }
    }

    // x registers aligned with C cells: idx (ms*4+nt)*4 + j
    float c[32], xr[32];
    #pragma unroll
    for (int ms = 0; ms < 2; ms++)
        #pragma unroll
        for (int nt = 0; nt < 4; nt++)
            #pragma unroll
            for (int j = 0; j < 4; j++) {
                int col = n0 + nt * 8 + (lane & 3) * 2 + (j & 1);
                xr[(ms * 4 + nt) * 4 + j] = state[col];
                c[(ms * 4 + nt) * 4 + j] = 0.f;
            }

    float win[4] = {0.f, 0.f, 0.f, 0.f};
    __syncthreads();   // all smem fills visible to all warps

    // ---- injection: c = x0@W^T + u0@B^T via hi pass (buf0) + lo pass (buf1)
    #pragma unroll
    for (int pass = 0; pass < 2; pass++) {
        const uint32_t aA0 = aA0b + pass * ZBYTES;
        const uint32_t aA1 = aA0 + 16 * LDZ * 2;
        #pragma unroll
        for (int ch = 0; ch < 10; ch++) {
            uint32_t a[8], b1[8], b2[8];
            ldm_x4(a,      aA0 + ch * 32);
            ldm_x4(a + 4,  aA1 + ch * 32);
            ldm_x4(b1,     aB0 + ch * 32);
            ldm_x4(b1 + 4, aB1 + ch * 32);
            ldm_x4(b2,     aB0 + 320 + ch * 32);
            ldm_x4(b2 + 4, aB1 + 320 + ch * 32);
            #pragma unroll
            for (int ms = 0; ms < 2; ms++)
                #pragma unroll
                for (int nt = 0; nt < 4; nt++) {
                    mma16816(&c[(ms * 4 + nt) * 4], &a[ms * 4], &b1[nt * 2]);
                    mma16816(&c[(ms * 4 + nt) * 4], &a[ms * 4], &b2[nt * 2]);
                }
        }
    }
    // now c = y_0.  Both Z buffers' injection reads are done group-locally
    // after each group's own mma issue; epilogue(t=0) rewrites only rows this
    // group wrote/read per the m-group locality.  A group barrier orders it.
    bar_grp(barid);

    // ---- main loop ----
    #pragma unroll 1
    for (int t = 0; t < H_DIM; t++) {
        const bool wrz = (t < H_DIM - 1);
        float4 f0, f1;
        if (wrz) {   // prefetch u_{t+1}; consumed at end of this epilogue
            f0 = *(const float4*)(up + (size_t)(t + 1) * C_DIM);
            f1 = *(const float4*)(up + (size_t)(t + 1) * C_DIM + 4);
        }
        const uint32_t zoffw = (uint32_t)(t & 1) * (ZBYTES / 4);  // word offset

        // epilogue: stage cost (x_t), x_{t+1} = x_t + dt*tanh(y_t), pack Dx
        #pragma unroll
        for (int ms = 0; ms < 2; ms++)
            #pragma unroll
            for (int nt = 0; nt < 4; nt++)
                #pragma unroll
                for (int h = 0; h < 2; h++) {
                    const int i0 = (ms * 4 + nt) * 4 + h * 2;
                    float x0v = xr[i0], x1v = xr[i0 + 1];
                    win[ms * 2 + h] += x0v * x0v + x1v * x1v;
                    float d0 = DT_F * tanh_fast(c[i0]);
                    float d1 = DT_F * tanh_fast(c[i0 + 1]);
                    xr[i0] = x0v + d0;
                    xr[i0 + 1] = x1v + d1;
                    if (wrz) {
                        int row = m0 + ms * 16 + h * 8 + (lane >> 2);
                        int wcol = (n0 >> 1) + nt * 4 + (lane & 3);
                        Zw[zoffw + row * LDZW + wcol] = pkh2(d0, d1);
                    }
                }

        if (wrz) {   // u_{t+1}: Du single fp16 with error feedback
            float uv[8] = {f0.x, f0.y, f0.z, f0.w, f1.x, f1.y, f1.z, f1.w};
            const float* pp = prev + (t + 1) * C_DIM + uq * 8;
            uint32_t dw[4];
            #pragma unroll
            for (int e = 0; e < 8; e += 2) {
                float ua = uv[e]     + (inh ? pp[e]     : 0.f);
                float ub = uv[e + 1] + (inh ? pp[e + 1] : 0.f);
                ua = fminf(fmaxf(ua, -2.f), 2.f);
                ub = fminf(fmaxf(ub, -2.f), 2.f);
                ucost += ua * ua + ub * ub;
                float sa = (ua - uold[e])     + ru[e];
                float sb = (ub - uold[e + 1]) + ru[e + 1];
                uold[e] = ua; uold[e + 1] = ub;
                __half2 hh = __floats2half2_rn(sa, sb);
                ru[e]     = sa - __half2float(__low2half(hh));
                ru[e + 1] = sb - __half2float(__high2half(hh));
                dw[e >> 1] = *(uint32_t*)&hh;
            }
            const int bh_ = zoffw + us * LDZW + 64 + uq * 4;
            #pragma unroll
            for (int e2 = 0; e2 < 4; e2++) Zw[bh_ + e2] = dw[e2];
        }

        if ((t & 7) == 7) {   // flush fp32 cost window into fp64
            #pragma unroll
            for (int i = 0; i < 4; i++) { s_cd[tid][i] += (double)win[i]; win[i] = 0.f; }
        }

        if (wrz) {
            bar_grp(barid);   // group's Z writes visible before its mma reads
            const uint32_t aA0 = aA0b + (t & 1) * ZBYTES;
            const uint32_t aA1 = aA0 + 16 * LDZ * 2;
            #pragma unroll
            for (int ch = 0; ch < 10; ch++) {
                uint32_t a[8], b1[8], b2[8];
                ldm_x4(a,      aA0 + ch * 32);
                ldm_x4(a + 4,  aA1 + ch * 32);
                ldm_x4(b1,     aB0 + ch * 32);
                ldm_x4(b1 + 4, aB1 + ch * 32);
                ldm_x4(b2,     aB0 + 320 + ch * 32);
                ldm_x4(b2 + 4, aB1 + 320 + ch * 32);
                #pragma unroll
                for (int ms = 0; ms < 2; ms++)
                    #pragma unroll
                    for (int nt = 0; nt < 4; nt++) {
                        mma16816(&c[(ms * 4 + nt) * 4], &a[ms * 4], &b1[nt * 2]);
                        mma16816(&c[(ms * 4 + nt) * 4], &a[ms * 4], &b2[nt * 2]);
                    }
            }
            bar_grp(barid);   // group's reads of this buffer done before next write
        }
    }

    // terminal ||x_H||^2 + final flush
    #pragma unroll
    for (int ms = 0; ms < 2; ms++)
        #pragma unroll
        for (int nt = 0; nt < 4; nt++)
            #pragma unroll
            for (int h = 0; h < 2; h++) {
                const int i0 = (ms * 4 + nt) * 4 + h * 2;
                win[ms * 2 + h] += xr[i0] * xr[i0] + xr[i0 + 1] * xr[i0 + 1];
            }
    #pragma unroll
    for (int i = 0; i < 4; i++) s_cd[tid][i] += (double)win[i];
    s_uc[uq][us] = ucost;
    __syncthreads();

    // per-sample cost assembly
    if (tid < MB) {
        const int s = tid;
        const int stIdx = ((s >> 4) & 1) * 2 + ((s >> 3) & 1);
        const int baseT = (s >> 5) * 128 + (s & 7) * 4;
        double cs = 0.0;
        #pragma unroll
        for (int wn = 0; wn < 4; wn++)
            #pragma unroll
            for (int b = 0; b < 4; b++)
                cs += s_cd[baseT + wn * 32 + b][stIdx];
        double uu = (double)s_uc[0][s] + s_uc[1][s] + s_uc[2][s] + s_uc[3][s];
        g_costs[n0g + s] = cs + 0.1 * uu;
    }
}

// ---------------------------------------------------------------------------
// K2: softmax over -costs (single block, fp64).
// ---------------------------------------------------------------------------
__global__ void k_softmax(int N)
{
    __shared__ double sm[1024];
    const int tid = threadIdx.x;
    double lmin = 1e300;
    for (int n = tid; n < N; n += 1024) lmin = fmin(lmin, g_costs[n]);
    sm[tid] = lmin; __syncthreads();
    for (int s = 512; s > 0; s >>= 1) {
        if (tid < s) sm[tid] = fmin(sm[tid], sm[tid + s]);
        __syncthreads();
    }
    double cmin = sm[0];
    __syncthreads();
    double ls = 0.0;
    for (int n = tid; n < N; n += 1024) {
        double w = exp(cmin - g_costs[n]);
        g_wtmp[n] = w; ls += w;
    }
    sm[tid] = ls; __syncthreads();
    for (int s = 512; s > 0; s >>= 1) {
        if (tid < s) sm[tid] += sm[tid + s];
        __syncthreads();
    }
    double inv = 1.0 / sm[0];
    for (int n = tid; n < N; n += 1024)
        g_weights[n] = (float)(g_wtmp[n] * inv);
}

// ---------------------------------------------------------------------------
// K3: partial weighted action sum with negligible-weight skip.
// ---------------------------------------------------------------------------
__global__ void k_wsum(const float* __restrict__ noises,
                       const float* __restrict__ prev, int thr, int N)
{
    const int ch = blockIdx.x, h = blockIdx.y;
    const int cc = threadIdx.x & 31, r = threadIdx.x >> 5;
    const int cnt = N / NCHUNK;
    const int n0 = ch * cnt;
    const float pv = prev[h * C_DIM + cc];
    double acc = 0.0;
    for (int nn = n0 + r; nn < n0 + cnt; nn += 8) {
        float w = g_weights[nn];
        if (w > 1e-12f) {
            float v = noises[((size_t)nn * H_DIM + h) * C_DIM + cc];
            if (nn < thr) v += pv;
            v = fminf(fmaxf(v, -2.f), 2.f);
            acc += (double)w * (double)v;
        }
    }
    __shared__ double s[8][33];
    s[r][cc] = acc; __syncthreads();
    if (r == 0) {
        double t = 0.0;
        #pragma unroll
        for (int i = 0; i < 8; i++) t += s[i][cc];
        g_part[(ch * H_DIM + h) * C_DIM + cc] = t;
    }
}

__global__ void k_afinal(float* __restrict__ outA)
{
    int idx = blockIdx.x * 1024 + threadIdx.x;
    if (idx >= H_DIM * C_DIM) return;
    double t = 0.0;
    #pragma unroll
    for (int ch = 0; ch < NCHUNK; ch++) t += g_part[ch * H_DIM * C_DIM + idx];
    outA[idx] = (float)t;
}

// ---------------------------------------------------------------------------
// K5: fp32 rollout of the optimal action sequence (single block).
// ---------------------------------------------------------------------------
__global__ __launch_bounds__(256, 1)
void k_opt(const float* __restrict__ state, const float* __restrict__ A,
           const float* __restrict__ Bm, const float* __restrict__ outA,
           float* __restrict__ outS)
{
    extern __shared__ float Ws[];     // [160][WPAD]
    __shared__ float xu[160];
    __shared__ float part[S_DIM];
    const int tid = threadIdx.x;
    const int s = tid & 127, half = tid >> 7;

    for (int idx = tid; idx < 160 * S_DIM; idx += 256) {
        int ss = idx / 160, k = idx - ss * 160;
        Ws[k * WPAD + ss] = (k < S_DIM) ? A[ss * S_DIM + k]
                                        : Bm[ss * C_DIM + (k - S_DIM)];
    }
    if (tid < S_DIM) {
        float x0 = state[tid];
        xu[tid] = x0;
        outS[tid] = x0;
    }
    for (int t = 0; t < H_DIM; t++) {
        if (tid < C_DIM) xu[S_DIM + tid] = outA[t * C_DIM + tid];
        __syncthreads();
        float acc = 0.f;
        const int k0 = half * 80;
        #pragma unroll 8
        for (int k = k0; k < k0 + 80; k++)
            acc = fmaf(xu[k], Ws[k * WPAD + s], acc);
        if (half) part[s] = acc;
        __syncthreads();
        if (!half) {
            float y = acc + part[s];
            float xn = xu[s] + DT_F * tanh_fast(y);
            xu[s] = xn;
            outS[(t + 1) * S_DIM + s] = xn;
        }
        __syncthreads();
    }
}

// ---------------------------------------------------------------------------
extern "C" void kernel_launch(void* const* d_in, const int* in_sizes, int n_in,
                              void* d_out, int out_size)
{
    const float* state  = (const float*)d_in[0];
    const float* A      = (const float*)d_in[1];
    const float* Bm     = (const float*)d_in[2];
    const float* noises = (const float*)d_in[3];
    const float* prev   = (const float*)d_in[4];

    int N = in_sizes[3] / (H_DIM * C_DIM);
    if (N > NMAX) N = NMAX;
    int thr = (int)((double)N * (1.0 - 0.2));

    float* outA = (float*)d_out;
    float* outS = outA + H_DIM * C_DIM;

    const int smem1 = 1024 + 2 * ZBYTES + 128 * LDW * 2;   // 171,008
    const int smem5 = 160 * WPAD * (int)sizeof(float);     // 84,480
    cudaFuncSetAttribute(k_roll, cudaFuncAttributeMaxDynamicSharedMemorySize, smem1);
    cudaFuncSetAttribute(k_opt,  cudaFuncAttributeMaxDynamicSharedMemorySize, smem5);

    k_roll<<<N / MB, 512, smem1>>>(state, A, Bm, noises, prev, thr);
    k_softmax<<<1, 1024>>>(N);
    dim3 g3(NCHUNK, H_DIM);
    k_wsum<<<g3, 256>>>(noises, prev, thr, N);
    k_afinal<<<2, 1024>>>(outA);
    k_opt<<<1, 256, smem5>>>(state, A, Bm, outA, outS);
}